// round 1
// baseline (speedup 1.0000x reference)
#include <cuda_runtime.h>
#include <math.h>

#define BATCH   16384
#define HID     512
#define NLAYERS 8
#define NOUT    16

#define WSCALE  4.4194173824159215e-04f  /* 0.01 / sqrt(512) */
#define BSCALE  0.01f
#define SLOPE   0.2f
#define GAIN    1.41421356237f           /* sqrt(2) */
#define EPSV    1e-8f

// Scratch ping-pong buffers (allocation-free rule: __device__ globals).
__device__ float g_bufA[BATCH * HID];
__device__ float g_bufB[BATCH * HID];

// ---------------------------------------------------------------------------
// Pixel norm: x * rsqrt(mean(x^2) + eps), one block (128 thr) per row of 512.
// ---------------------------------------------------------------------------
__global__ void pixelnorm_kernel(const float* __restrict__ z,
                                 float* __restrict__ out) {
    const int row = blockIdx.x;
    const int tid = threadIdx.x;  // 128 threads, 4 floats each
    float4 v = ((const float4*)(z + (size_t)row * HID))[tid];
    float s = v.x * v.x + v.y * v.y + v.z * v.z + v.w * v.w;
#pragma unroll
    for (int o = 16; o > 0; o >>= 1) s += __shfl_xor_sync(0xffffffffu, s, o);
    __shared__ float ws[4];
    if ((tid & 31) == 0) ws[tid >> 5] = s;
    __syncthreads();
    float tot = ws[0] + ws[1] + ws[2] + ws[3];
    float r = rsqrtf(tot * (1.0f / HID) + EPSV);
    v.x *= r; v.y *= r; v.z *= r; v.w *= r;
    ((float4*)(out + (size_t)row * HID))[tid] = v;
}

// ---------------------------------------------------------------------------
// One dense layer: C[b,o] = lrelu( sum_k A[b,k] * W[o,k] * WSCALE + bias[o]*BSCALE ) * GAIN
// Tiles: 128x128 block, BK=16, 256 threads, 8x8 per-thread micro-tile.
// LAST=true writes the 16x broadcast straight into d_out [B, 16, 512].
// ---------------------------------------------------------------------------
template <bool LAST>
__global__ __launch_bounds__(256)
void layer_gemm(const float* __restrict__ A, const float* __restrict__ W,
                const float* __restrict__ bias, float* __restrict__ out) {
    constexpr int BM = 128, BN = 128, BK = 16;
    __shared__ float As[BK][BM + 4];
    __shared__ float Bs[BK][BN + 4];

    const int tid = threadIdx.x;
    const int tx = tid & 15;        // 0..15 -> n
    const int ty = tid >> 4;        // 0..15 -> m
    const int bm = blockIdx.y * BM;
    const int bn = blockIdx.x * BN;

    // Load mapping: 256 threads, each loads float4 from 64 rows x 16 k per pass
    const int lr = tid >> 2;          // 0..63
    const int lc = (tid & 3) << 2;    // 0,4,8,12
    const float* Ag = A + (size_t)(bm + lr) * HID + lc;
    const float* Wg = W + (size_t)(bn + lr) * HID + lc;

    float acc[8][8] = {};

    for (int k0 = 0; k0 < HID; k0 += BK) {
#pragma unroll
        for (int h = 0; h < 2; h++) {
            float4 a = *(const float4*)(Ag + (size_t)h * 64 * HID + k0);
            As[lc + 0][lr + h * 64] = a.x;
            As[lc + 1][lr + h * 64] = a.y;
            As[lc + 2][lr + h * 64] = a.z;
            As[lc + 3][lr + h * 64] = a.w;
            float4 w = *(const float4*)(Wg + (size_t)h * 64 * HID + k0);
            Bs[lc + 0][lr + h * 64] = w.x;
            Bs[lc + 1][lr + h * 64] = w.y;
            Bs[lc + 2][lr + h * 64] = w.z;
            Bs[lc + 3][lr + h * 64] = w.w;
        }
        __syncthreads();
#pragma unroll
        for (int kk = 0; kk < BK; kk++) {
            float ra[8], rb[8];
#pragma unroll
            for (int i = 0; i < 8; i++) ra[i] = As[kk][ty * 8 + i];
#pragma unroll
            for (int j = 0; j < 8; j++) rb[j] = Bs[kk][tx * 8 + j];
#pragma unroll
            for (int i = 0; i < 8; i++)
#pragma unroll
                for (int j = 0; j < 8; j++)
                    acc[i][j] = fmaf(ra[i], rb[j], acc[i][j]);
        }
        __syncthreads();
    }

    float bj[8];
#pragma unroll
    for (int j = 0; j < 8; j++) bj[j] = bias[bn + tx * 8 + j] * BSCALE;

#pragma unroll
    for (int i = 0; i < 8; i++) {
        const int row = bm + ty * 8 + i;
        float v[8];
#pragma unroll
        for (int j = 0; j < 8; j++) {
            float x = acc[i][j] * WSCALE + bj[j];
            x = (x > 0.0f ? x : SLOPE * x) * GAIN;
            v[j] = x;
        }
        float4 p0 = make_float4(v[0], v[1], v[2], v[3]);
        float4 p1 = make_float4(v[4], v[5], v[6], v[7]);
        if (!LAST) {
            float4* dst = (float4*)(out + (size_t)row * HID + bn + tx * 8);
            dst[0] = p0;
            dst[1] = p1;
        } else {
#pragma unroll
            for (int r = 0; r < NOUT; r++) {
                float4* dst =
                    (float4*)(out + ((size_t)row * NOUT + r) * HID + bn + tx * 8);
                dst[0] = p0;
                dst[1] = p1;
            }
        }
    }
}

// ---------------------------------------------------------------------------
extern "C" void kernel_launch(void* const* d_in, const int* in_sizes, int n_in,
                              void* d_out, int out_size) {
    const float* z      = (const float*)d_in[0];
    const float* weight = (const float*)d_in[1];
    const float* bias   = (const float*)d_in[2];
    float* out = (float*)d_out;

    float *bufA, *bufB;
    cudaGetSymbolAddress((void**)&bufA, g_bufA);
    cudaGetSymbolAddress((void**)&bufB, g_bufB);

    pixelnorm_kernel<<<BATCH, 128>>>(z, bufA);

    dim3 grid(HID / 128, BATCH / 128);  // (4, 128) = 512 CTAs
    for (int l = 0; l < NLAYERS; l++) {
        const float* in = (l & 1) ? bufB : bufA;
        float* o        = (l & 1) ? bufA : bufB;
        const float* Wl = weight + (size_t)l * HID * HID;
        const float* bl = bias + (size_t)l * HID;
        if (l == NLAYERS - 1)
            layer_gemm<true><<<grid, 256>>>(in, Wl, bl, out);
        else
            layer_gemm<false><<<grid, 256>>>(in, Wl, bl, o);
    }
}

// round 3
// speedup vs baseline: 2.1934x; 2.1934x over previous
#include <cuda_runtime.h>
#include <cuda_fp16.h>
#include <cstdint>

#define BATCH   16384
#define HID     512
#define NLAYERS 8
#define NOUT    16
#define WSCALE  4.4194173824159215e-04f  /* 0.01 / sqrt(512) */
#define BSCALE  0.01f
#define SLOPE   0.2f
#define GAIN    1.41421356237f
#define EPSV    1e-8f

// ---------------------------------------------------------------------------
// Scratch (allocation-free rule: __device__ globals)
// ---------------------------------------------------------------------------
__device__ __half g_Ahi[2][(size_t)BATCH * HID];
__device__ __half g_Alo[2][(size_t)BATCH * HID];
__device__ __half g_Whi[(size_t)NLAYERS * HID * HID];
__device__ __half g_Wlo[(size_t)NLAYERS * HID * HID];

// ---------------------------------------------------------------------------
// Helpers
// ---------------------------------------------------------------------------
__device__ __forceinline__ uint32_t smem_u32(const void* p) {
    uint32_t a;
    asm("{ .reg .u64 t; cvta.to.shared.u64 t, %1; cvt.u32.u64 %0, t; }"
        : "=r"(a) : "l"(p));
    return a;
}
__device__ __forceinline__ void ldm_x4(uint32_t addr, uint32_t r[4]) {
    asm volatile(
        "ldmatrix.sync.aligned.m8n8.x4.shared.b16 {%0,%1,%2,%3}, [%4];"
        : "=r"(r[0]), "=r"(r[1]), "=r"(r[2]), "=r"(r[3]) : "r"(addr));
}
__device__ __forceinline__ void mma16816(float c[4], const uint32_t a[4],
                                         const uint32_t b[2]) {
    asm volatile(
        "mma.sync.aligned.m16n8k16.row.col.f32.f16.f16.f32 "
        "{%0,%1,%2,%3}, {%4,%5,%6,%7}, {%8,%9}, {%0,%1,%2,%3};"
        : "+f"(c[0]), "+f"(c[1]), "+f"(c[2]), "+f"(c[3])
        : "r"(a[0]), "r"(a[1]), "r"(a[2]), "r"(a[3]), "r"(b[0]), "r"(b[1]));
}
#define CP_ASYNC16(sa, ga) \
    asm volatile("cp.async.cg.shared.global [%0], [%1], 16;" :: "r"(sa), "l"(ga))
#define CP_COMMIT() asm volatile("cp.async.commit_group;")
#define CP_WAIT1() asm volatile("cp.async.wait_group 1;")
#define CP_WAIT0() asm volatile("cp.async.wait_group 0;")

// ---------------------------------------------------------------------------
// Weight conversion: w_eff = w * WSCALE, split fp16 hi + lo
// ---------------------------------------------------------------------------
__global__ void wconv_kernel(const float* __restrict__ w,
                             __half* __restrict__ whi,
                             __half* __restrict__ wlo) {
    size_t i = (size_t)blockIdx.x * blockDim.x + threadIdx.x;
    float4 v = ((const float4*)w)[i];
    float e[4] = {v.x * WSCALE, v.y * WSCALE, v.z * WSCALE, v.w * WSCALE};
    union { uint2 u; __half h[4]; } ph, pl;
#pragma unroll
    for (int j = 0; j < 4; j++) {
        __half hh = __float2half_rn(e[j]);
        ph.h[j] = hh;
        pl.h[j] = __float2half_rn(e[j] - __half2float(hh));
    }
    ((uint2*)whi)[i] = ph.u;
    ((uint2*)wlo)[i] = pl.u;
}

// ---------------------------------------------------------------------------
// Pixel norm + fp16 hi/lo split
// ---------------------------------------------------------------------------
__global__ void pixelnorm_split_kernel(const float* __restrict__ z,
                                       __half* __restrict__ ahi,
                                       __half* __restrict__ alo) {
    const int row = blockIdx.x;
    const int tid = threadIdx.x;
    float4 v = ((const float4*)(z + (size_t)row * HID))[tid];
    float s = v.x * v.x + v.y * v.y + v.z * v.z + v.w * v.w;
#pragma unroll
    for (int o = 16; o > 0; o >>= 1) s += __shfl_xor_sync(0xffffffffu, s, o);
    __shared__ float ws[4];
    if ((tid & 31) == 0) ws[tid >> 5] = s;
    __syncthreads();
    float tot = ws[0] + ws[1] + ws[2] + ws[3];
    float r = rsqrtf(tot * (1.0f / HID) + EPSV);
    float e[4] = {v.x * r, v.y * r, v.z * r, v.w * r};
    union { uint2 u; __half h[4]; } ph, pl;
#pragma unroll
    for (int j = 0; j < 4; j++) {
        __half hh = __float2half_rn(e[j]);
        ph.h[j] = hh;
        pl.h[j] = __float2half_rn(e[j] - __half2float(hh));
    }
    size_t off = ((size_t)row * HID) / 4 + tid;
    ((uint2*)ahi)[off] = ph.u;
    ((uint2*)alo)[off] = pl.u;
}

// ---------------------------------------------------------------------------
// HMMA split-fp16 GEMM layer.  C[m,n] = sum_k a[m,k] * w_eff[n,k]
// 3 terms: hi*hi + hi*lo + lo*hi, fp32 accum.
// Tile 128x128, BK=32, 256 threads (2x4 warps, 64x32 per warp).
// SMEM tiles: 128 rows x 32 half, row stride 80 B (conflict-free ldmatrix).
// ---------------------------------------------------------------------------
#define RSTRIDE 80
#define TILE_BYTES (128 * RSTRIDE)       /* 10240 */
#define STAGE_BYTES (4 * TILE_BYTES)     /* 40960 */
#define SMEM_TOTAL (2 * STAGE_BYTES)     /* 81920 */
#define OFF_AH 0
#define OFF_AL TILE_BYTES
#define OFF_BH (2 * TILE_BYTES)
#define OFF_BL (3 * TILE_BYTES)

__device__ __forceinline__ void load_tile(uint32_t sbase,
                                          const __half* __restrict__ g,
                                          int rowbase, int kbase, int tid) {
#pragma unroll
    for (int h = 0; h < 2; h++) {
        int u = tid + h * 256;          // 0..511
        int row = u >> 2;
        int un = u & 3;
        uint32_t sa = sbase + row * RSTRIDE + un * 16;
        const void* ga = g + (size_t)(rowbase + row) * HID + kbase + un * 8;
        CP_ASYNC16(sa, ga);
    }
}

template <bool LAST>
__global__ __launch_bounds__(256, 1) void gemm_layer(
    const __half* __restrict__ Ahi, const __half* __restrict__ Alo,
    const __half* __restrict__ Whi, const __half* __restrict__ Wlo,
    const float* __restrict__ bias, __half* __restrict__ Ohi,
    __half* __restrict__ Olo, float* __restrict__ OutF) {
    extern __shared__ char smem[];
    const uint32_t sb = smem_u32(smem);
    const int tid = threadIdx.x;
    const int wid = tid >> 5;
    const int lid = tid & 31;
    const int wm = wid >> 2;            // 0..1 -> 64 rows
    const int wn = wid & 3;             // 0..3 -> 32 cols
    const int bm = blockIdx.y * 128;
    const int bn = blockIdx.x * 128;

    // ldmatrix lane decomposition
    const int lt = lid >> 3;            // tile index 0..3
    const int li = lid & 7;             // row within 8x8 tile

    float acc[4][4][4];
#pragma unroll
    for (int a = 0; a < 4; a++)
#pragma unroll
        for (int b = 0; b < 4; b++)
#pragma unroll
            for (int c = 0; c < 4; c++) acc[a][b][c] = 0.0f;

    // prologue
    {
        uint32_t s0 = sb;
        load_tile(s0 + OFF_AH, Ahi, bm, 0, tid);
        load_tile(s0 + OFF_AL, Alo, bm, 0, tid);
        load_tile(s0 + OFF_BH, Whi, bn, 0, tid);
        load_tile(s0 + OFF_BL, Wlo, bn, 0, tid);
        CP_COMMIT();
    }

    for (int s = 0; s < 16; s++) {
        if (s + 1 < 16) {
            uint32_t sn = sb + ((s + 1) & 1) * STAGE_BYTES;
            int kb = (s + 1) * 32;
            load_tile(sn + OFF_AH, Ahi, bm, kb, tid);
            load_tile(sn + OFF_AL, Alo, bm, kb, tid);
            load_tile(sn + OFF_BH, Whi, bn, kb, tid);
            load_tile(sn + OFF_BL, Wlo, bn, kb, tid);
            CP_COMMIT();
            CP_WAIT1();
        } else {
            CP_WAIT0();
        }
        __syncthreads();

        uint32_t sc = sb + (s & 1) * STAGE_BYTES;
#pragma unroll
        for (int kk = 0; kk < 2; kk++) {
            // A fragments: tile t -> m_off=(t&1)*8, k_off=(t>>1)*8
            const int am_row = wm * 64 + (lt & 1) * 8 + li;
            const int ak = kk * 16 + (lt >> 1) * 8;
            uint32_t ah[4][4], al[4][4];
#pragma unroll
            for (int mf = 0; mf < 4; mf++) {
                uint32_t addr =
                    sc + OFF_AH + (am_row + mf * 16) * RSTRIDE + ak * 2;
                ldm_x4(addr, ah[mf]);
                ldm_x4(addr + (OFF_AL - OFF_AH), al[mf]);
            }
            // B fragments: tile t -> n_off=(t>>1)*8, k_off=(t&1)*8
            const int bn_row = wn * 32 + (lt >> 1) * 8 + li;
            const int bk = kk * 16 + (lt & 1) * 8;
            uint32_t bh[4][2], bl[4][2];
#pragma unroll
            for (int p = 0; p < 2; p++) {
                uint32_t addr =
                    sc + OFF_BH + (bn_row + p * 16) * RSTRIDE + bk * 2;
                uint32_t r[4];
                ldm_x4(addr, r);
                bh[2 * p][0] = r[0]; bh[2 * p][1] = r[1];
                bh[2 * p + 1][0] = r[2]; bh[2 * p + 1][1] = r[3];
                ldm_x4(addr + (OFF_BL - OFF_BH), r);
                bl[2 * p][0] = r[0]; bl[2 * p][1] = r[1];
                bl[2 * p + 1][0] = r[2]; bl[2 * p + 1][1] = r[3];
            }
#pragma unroll
            for (int mf = 0; mf < 4; mf++)
#pragma unroll
                for (int nf = 0; nf < 4; nf++) {
                    mma16816(acc[mf][nf], ah[mf], bh[nf]);
                    mma16816(acc[mf][nf], ah[mf], bl[nf]);
                    mma16816(acc[mf][nf], al[mf], bh[nf]);
                }
        }
        __syncthreads();
    }

    // Epilogue: c mapping for m16n8: reg e -> row=(l/4)+(e>=2?8:0),
    // col=(l%4)*2+(e&1)
    float bj[4][2];
#pragma unroll
    for (int nf = 0; nf < 4; nf++) {
        int col = bn + wn * 32 + nf * 8 + (lid & 3) * 2;
        bj[nf][0] = bias[col] * BSCALE;
        bj[nf][1] = bias[col + 1] * BSCALE;
    }

#pragma unroll
    for (int mf = 0; mf < 4; mf++) {
#pragma unroll
        for (int half_ : {0, 1}) {
            int row = bm + wm * 64 + mf * 16 + (lid >> 2) + half_ * 8;
#pragma unroll
            for (int nf = 0; nf < 4; nf++) {
                int col = bn + wn * 32 + nf * 8 + (lid & 3) * 2;
                float x0 = acc[mf][nf][half_ * 2 + 0] + bj[nf][0];
                float x1 = acc[mf][nf][half_ * 2 + 1] + bj[nf][1];
                x0 = (x0 > 0.0f ? x0 : SLOPE * x0) * GAIN;
                x1 = (x1 > 0.0f ? x1 : SLOPE * x1) * GAIN;
                if (!LAST) {
                    __half h0 = __float2half_rn(x0);
                    __half h1 = __float2half_rn(x1);
                    __half l0 = __float2half_rn(x0 - __half2float(h0));
                    __half l1 = __float2half_rn(x1 - __half2float(h1));
                    size_t off = (size_t)row * HID + col;
                    *(__half2*)(Ohi + off) = __halves2half2(h0, h1);
                    *(__half2*)(Olo + off) = __halves2half2(l0, l1);
                } else {
                    float2 p = make_float2(x0, x1);
#pragma unroll
                    for (int r = 0; r < NOUT; r++) {
                        size_t off = ((size_t)row * NOUT + r) * HID + col;
                        *(float2*)(OutF + off) = p;
                    }
                }
            }
        }
    }
}

// ---------------------------------------------------------------------------
extern "C" void kernel_launch(void* const* d_in, const int* in_sizes, int n_in,
                              void* d_out, int out_size) {
    const float* z = (const float*)d_in[0];
    const float* weight = (const float*)d_in[1];
    const float* bias = (const float*)d_in[2];
    float* out = (float*)d_out;

    __half *ahi, *alo, *whi, *wlo;
    cudaGetSymbolAddress((void**)&ahi, g_Ahi);
    cudaGetSymbolAddress((void**)&alo, g_Alo);
    cudaGetSymbolAddress((void**)&whi, g_Whi);
    cudaGetSymbolAddress((void**)&wlo, g_Wlo);

    cudaFuncSetAttribute(gemm_layer<false>,
                         cudaFuncAttributeMaxDynamicSharedMemorySize, SMEM_TOTAL);
    cudaFuncSetAttribute(gemm_layer<true>,
                         cudaFuncAttributeMaxDynamicSharedMemorySize, SMEM_TOTAL);

    wconv_kernel<<<2048, 256>>>(weight, whi, wlo);
    pixelnorm_split_kernel<<<BATCH, 128>>>(z, ahi, alo);

    const size_t ABUF = (size_t)BATCH * HID;
    dim3 grid(HID / 128, BATCH / 128);  // (4, 128)
    for (int l = 0; l < NLAYERS; l++) {
        const __half* Ah = ahi + (l & 1) * ABUF;
        const __half* Al = alo + (l & 1) * ABUF;
        __half* Oh = ahi + ((l + 1) & 1) * ABUF;
        __half* Ol = alo + ((l + 1) & 1) * ABUF;
        const __half* Wh = whi + (size_t)l * HID * HID;
        const __half* Wl = wlo + (size_t)l * HID * HID;
        const float* bl = bias + (size_t)l * HID;
        if (l == NLAYERS - 1)
            gemm_layer<true><<<grid, 256, SMEM_TOTAL>>>(Ah, Al, Wh, Wl, bl,
                                                        nullptr, nullptr, out);
        else
            gemm_layer<false><<<grid, 256, SMEM_TOTAL>>>(Ah, Al, Wh, Wl, bl,
                                                         Oh, Ol, nullptr);
    }
}

// round 4
// speedup vs baseline: 2.4755x; 1.1286x over previous
#include <cuda_runtime.h>
#include <cuda_fp16.h>
#include <cstdint>

#define BATCH   16384
#define HID     512
#define NLAYERS 8
#define NOUT    16
#define WSCALE  4.4194173824159215e-04f  /* 0.01 / sqrt(512) */
#define BSCALE  0.01f
#define SLOPE   0.2f
#define GAIN    1.41421356237f
#define EPSV    1e-8f

// ---------------------------------------------------------------------------
// Scratch (allocation-free rule: __device__ globals)
// ---------------------------------------------------------------------------
__device__ __half g_Ahi[2][(size_t)BATCH * HID];
__device__ __half g_Alo[2][(size_t)BATCH * HID];
__device__ __half g_Whi[(size_t)NLAYERS * HID * HID];
__device__ __half g_Wlo[(size_t)NLAYERS * HID * HID];

// ---------------------------------------------------------------------------
// Helpers
// ---------------------------------------------------------------------------
__device__ __forceinline__ uint32_t smem_u32(const void* p) {
    uint32_t a;
    asm("{ .reg .u64 t; cvta.to.shared.u64 t, %1; cvt.u32.u64 %0, t; }"
        : "=r"(a) : "l"(p));
    return a;
}
__device__ __forceinline__ void ldm_x4(uint32_t addr, uint32_t r[4]) {
    asm volatile(
        "ldmatrix.sync.aligned.m8n8.x4.shared.b16 {%0,%1,%2,%3}, [%4];"
        : "=r"(r[0]), "=r"(r[1]), "=r"(r[2]), "=r"(r[3]) : "r"(addr));
}
__device__ __forceinline__ void mma16816(float c[4], const uint32_t a[4],
                                         const uint32_t b[2]) {
    asm volatile(
        "mma.sync.aligned.m16n8k16.row.col.f32.f16.f16.f32 "
        "{%0,%1,%2,%3}, {%4,%5,%6,%7}, {%8,%9}, {%0,%1,%2,%3};"
        : "+f"(c[0]), "+f"(c[1]), "+f"(c[2]), "+f"(c[3])
        : "r"(a[0]), "r"(a[1]), "r"(a[2]), "r"(a[3]), "r"(b[0]), "r"(b[1]));
}
#define CP_ASYNC16(sa, ga) \
    asm volatile("cp.async.cg.shared.global [%0], [%1], 16;" :: "r"(sa), "l"(ga))
#define CP_COMMIT() asm volatile("cp.async.commit_group;")
#define CP_WAIT1() asm volatile("cp.async.wait_group 1;")
#define CP_WAIT0() asm volatile("cp.async.wait_group 0;")

// ---------------------------------------------------------------------------
// Weight conversion: w_eff = w * WSCALE, split fp16 hi + lo
// ---------------------------------------------------------------------------
__global__ void wconv_kernel(const float* __restrict__ w,
                             __half* __restrict__ whi,
                             __half* __restrict__ wlo) {
    size_t i = (size_t)blockIdx.x * blockDim.x + threadIdx.x;
    float4 v = ((const float4*)w)[i];
    float e[4] = {v.x * WSCALE, v.y * WSCALE, v.z * WSCALE, v.w * WSCALE};
    union { uint2 u; __half h[4]; } ph, pl;
#pragma unroll
    for (int j = 0; j < 4; j++) {
        __half hh = __float2half_rn(e[j]);
        ph.h[j] = hh;
        pl.h[j] = __float2half_rn(e[j] - __half2float(hh));
    }
    ((uint2*)whi)[i] = ph.u;
    ((uint2*)wlo)[i] = pl.u;
}

// ---------------------------------------------------------------------------
// Pixel norm + fp16 hi/lo split
// ---------------------------------------------------------------------------
__global__ void pixelnorm_split_kernel(const float* __restrict__ z,
                                       __half* __restrict__ ahi,
                                       __half* __restrict__ alo) {
    const int row = blockIdx.x;
    const int tid = threadIdx.x;
    float4 v = ((const float4*)(z + (size_t)row * HID))[tid];
    float s = v.x * v.x + v.y * v.y + v.z * v.z + v.w * v.w;
#pragma unroll
    for (int o = 16; o > 0; o >>= 1) s += __shfl_xor_sync(0xffffffffu, s, o);
    __shared__ float ws[4];
    if ((tid & 31) == 0) ws[tid >> 5] = s;
    __syncthreads();
    float tot = ws[0] + ws[1] + ws[2] + ws[3];
    float r = rsqrtf(tot * (1.0f / HID) + EPSV);
    float e[4] = {v.x * r, v.y * r, v.z * r, v.w * r};
    union { uint2 u; __half h[4]; } ph, pl;
#pragma unroll
    for (int j = 0; j < 4; j++) {
        __half hh = __float2half_rn(e[j]);
        ph.h[j] = hh;
        pl.h[j] = __float2half_rn(e[j] - __half2float(hh));
    }
    size_t off = ((size_t)row * HID) / 4 + tid;
    ((uint2*)ahi)[off] = ph.u;
    ((uint2*)alo)[off] = pl.u;
}

// ---------------------------------------------------------------------------
// HMMA split-fp16 GEMM layer.  C[m,n] = sum_k a[m,k] * w_eff[n,k]
// 3 terms: hi*hi + hi*lo + lo*hi, fp32 accum.
// Tile 128x128, BK=32, 256 threads (2x4 warps, 64x32 per warp), 2 CTAs/SM.
// SMEM tiles: 128 rows x 32 half, row stride 80 B (conflict-free ldmatrix).
// ---------------------------------------------------------------------------
#define RSTRIDE 80
#define TILE_BYTES (128 * RSTRIDE)       /* 10240 */
#define STAGE_BYTES (4 * TILE_BYTES)     /* 40960 */
#define SMEM_TOTAL (2 * STAGE_BYTES)     /* 81920 */
#define OFF_AH 0
#define OFF_AL TILE_BYTES
#define OFF_BH (2 * TILE_BYTES)
#define OFF_BL (3 * TILE_BYTES)

__device__ __forceinline__ void load_tile(uint32_t sbase,
                                          const __half* __restrict__ g,
                                          int rowbase, int kbase, int tid) {
#pragma unroll
    for (int h = 0; h < 2; h++) {
        int u = tid + h * 256;          // 0..511
        int row = u >> 2;
        int un = u & 3;
        uint32_t sa = sbase + row * RSTRIDE + un * 16;
        const void* ga = g + (size_t)(rowbase + row) * HID + kbase + un * 8;
        CP_ASYNC16(sa, ga);
    }
}

template <bool LAST>
__global__ __launch_bounds__(256, 2) void gemm_layer(
    const __half* __restrict__ Ahi, const __half* __restrict__ Alo,
    const __half* __restrict__ Whi, const __half* __restrict__ Wlo,
    const float* __restrict__ bias, __half* __restrict__ Ohi,
    __half* __restrict__ Olo, float* __restrict__ OutF) {
    extern __shared__ char smem[];
    const uint32_t sb = smem_u32(smem);
    const int tid = threadIdx.x;
    const int wid = tid >> 5;
    const int lid = tid & 31;
    const int wm = wid >> 2;            // 0..1 -> 64 rows
    const int wn = wid & 3;             // 0..3 -> 32 cols
    const int bm = blockIdx.y * 128;
    const int bn = blockIdx.x * 128;

    // ldmatrix lane decomposition
    const int lt = lid >> 3;            // tile index 0..3
    const int li = lid & 7;             // row within 8x8 tile

    float acc[4][4][4];
#pragma unroll
    for (int a = 0; a < 4; a++)
#pragma unroll
        for (int b = 0; b < 4; b++)
#pragma unroll
            for (int c = 0; c < 4; c++) acc[a][b][c] = 0.0f;

    // prologue
    {
        uint32_t s0 = sb;
        load_tile(s0 + OFF_AH, Ahi, bm, 0, tid);
        load_tile(s0 + OFF_AL, Alo, bm, 0, tid);
        load_tile(s0 + OFF_BH, Whi, bn, 0, tid);
        load_tile(s0 + OFF_BL, Wlo, bn, 0, tid);
        CP_COMMIT();
    }

    for (int s = 0; s < 16; s++) {
        if (s + 1 < 16) {
            uint32_t sn = sb + ((s + 1) & 1) * STAGE_BYTES;
            int kb = (s + 1) * 32;
            load_tile(sn + OFF_AH, Ahi, bm, kb, tid);
            load_tile(sn + OFF_AL, Alo, bm, kb, tid);
            load_tile(sn + OFF_BH, Whi, bn, kb, tid);
            load_tile(sn + OFF_BL, Wlo, bn, kb, tid);
            CP_COMMIT();
            CP_WAIT1();
        } else {
            CP_WAIT0();
        }
        __syncthreads();

        uint32_t sc = sb + (s & 1) * STAGE_BYTES;
#pragma unroll
        for (int kk = 0; kk < 2; kk++) {
            // A fragments: tile t -> m_off=(t&1)*8, k_off=(t>>1)*8
            const int am_row = wm * 64 + (lt & 1) * 8 + li;
            const int ak = kk * 16 + (lt >> 1) * 8;
            uint32_t ah[4][4], al[4][4];
#pragma unroll
            for (int mf = 0; mf < 4; mf++) {
                uint32_t addr =
                    sc + OFF_AH + (am_row + mf * 16) * RSTRIDE + ak * 2;
                ldm_x4(addr, ah[mf]);
                ldm_x4(addr + (OFF_AL - OFF_AH), al[mf]);
            }
            // B fragments, processed in two n-halves (keeps regs < 128):
            // half h covers nf = 2h, 2h+1
            const int bn_row0 = wn * 32 + (lt >> 1) * 8 + li;
            const int bk = kk * 16 + (lt & 1) * 8;
#pragma unroll
            for (int h = 0; h < 2; h++) {
                uint32_t bh2[2][2], bl2[2][2];
                uint32_t addr =
                    sc + OFF_BH + (bn_row0 + h * 16) * RSTRIDE + bk * 2;
                uint32_t r[4];
                ldm_x4(addr, r);
                bh2[0][0] = r[0]; bh2[0][1] = r[1];
                bh2[1][0] = r[2]; bh2[1][1] = r[3];
                ldm_x4(addr + (OFF_BL - OFF_BH), r);
                bl2[0][0] = r[0]; bl2[0][1] = r[1];
                bl2[1][0] = r[2]; bl2[1][1] = r[3];
                // term-outer ordering: 8 independent accs between same-acc
                // reuse (no back-to-back RAW on the accumulator)
#pragma unroll
                for (int mf = 0; mf < 4; mf++)
#pragma unroll
                    for (int nl = 0; nl < 2; nl++)
                        mma16816(acc[mf][h * 2 + nl], ah[mf], bh2[nl]);
#pragma unroll
                for (int mf = 0; mf < 4; mf++)
#pragma unroll
                    for (int nl = 0; nl < 2; nl++)
                        mma16816(acc[mf][h * 2 + nl], ah[mf], bl2[nl]);
#pragma unroll
                for (int mf = 0; mf < 4; mf++)
#pragma unroll
                    for (int nl = 0; nl < 2; nl++)
                        mma16816(acc[mf][h * 2 + nl], al[mf], bh2[nl]);
            }
        }
        __syncthreads();
    }

    // Epilogue: c mapping for m16n8: reg e -> row=(l/4)+(e>=2?8:0),
    // col=(l%4)*2+(e&1)
    float bj[4][2];
#pragma unroll
    for (int nf = 0; nf < 4; nf++) {
        int col = bn + wn * 32 + nf * 8 + (lid & 3) * 2;
        bj[nf][0] = bias[col] * BSCALE;
        bj[nf][1] = bias[col + 1] * BSCALE;
    }

#pragma unroll
    for (int mf = 0; mf < 4; mf++) {
#pragma unroll
        for (int half_ : {0, 1}) {
            int row = bm + wm * 64 + mf * 16 + (lid >> 2) + half_ * 8;
#pragma unroll
            for (int nf = 0; nf < 4; nf++) {
                int col = bn + wn * 32 + nf * 8 + (lid & 3) * 2;
                float x0 = acc[mf][nf][half_ * 2 + 0] + bj[nf][0];
                float x1 = acc[mf][nf][half_ * 2 + 1] + bj[nf][1];
                x0 = (x0 > 0.0f ? x0 : SLOPE * x0) * GAIN;
                x1 = (x1 > 0.0f ? x1 : SLOPE * x1) * GAIN;
                if (!LAST) {
                    __half h0 = __float2half_rn(x0);
                    __half h1 = __float2half_rn(x1);
                    __half l0 = __float2half_rn(x0 - __half2float(h0));
                    __half l1 = __float2half_rn(x1 - __half2float(h1));
                    size_t off = (size_t)row * HID + col;
                    *(__half2*)(Ohi + off) = __halves2half2(h0, h1);
                    *(__half2*)(Olo + off) = __halves2half2(l0, l1);
                } else {
                    float2 p = make_float2(x0, x1);
#pragma unroll
                    for (int r = 0; r < NOUT; r++) {
                        size_t off = ((size_t)row * NOUT + r) * HID + col;
                        *(float2*)(OutF + off) = p;
                    }
                }
            }
        }
    }
}

// ---------------------------------------------------------------------------
extern "C" void kernel_launch(void* const* d_in, const int* in_sizes, int n_in,
                              void* d_out, int out_size) {
    const float* z = (const float*)d_in[0];
    const float* weight = (const float*)d_in[1];
    const float* bias = (const float*)d_in[2];
    float* out = (float*)d_out;

    __half *ahi, *alo, *whi, *wlo;
    cudaGetSymbolAddress((void**)&ahi, g_Ahi);
    cudaGetSymbolAddress((void**)&alo, g_Alo);
    cudaGetSymbolAddress((void**)&whi, g_Whi);
    cudaGetSymbolAddress((void**)&wlo, g_Wlo);

    cudaFuncSetAttribute(gemm_layer<false>,
                         cudaFuncAttributeMaxDynamicSharedMemorySize, SMEM_TOTAL);
    cudaFuncSetAttribute(gemm_layer<true>,
                         cudaFuncAttributeMaxDynamicSharedMemorySize, SMEM_TOTAL);

    wconv_kernel<<<2048, 256>>>(weight, whi, wlo);
    pixelnorm_split_kernel<<<BATCH, 128>>>(z, ahi, alo);

    const size_t ABUF = (size_t)BATCH * HID;
    dim3 grid(HID / 128, BATCH / 128);  // (4, 128)
    for (int l = 0; l < NLAYERS; l++) {
        const __half* Ah = ahi + (l & 1) * ABUF;
        const __half* Al = alo + (l & 1) * ABUF;
        __half* Oh = ahi + ((l + 1) & 1) * ABUF;
        __half* Ol = alo + ((l + 1) & 1) * ABUF;
        const __half* Wh = whi + (size_t)l * HID * HID;
        const __half* Wl = wlo + (size_t)l * HID * HID;
        const float* bl = bias + (size_t)l * HID;
        if (l == NLAYERS - 1)
            gemm_layer<true><<<grid, 256, SMEM_TOTAL>>>(Ah, Al, Wh, Wl, bl,
                                                        nullptr, nullptr, out);
        else
            gemm_layer<false><<<grid, 256, SMEM_TOTAL>>>(Ah, Al, Wh, Wl, bl,
                                                         Oh, Ol, nullptr);
    }
}

// round 5
// speedup vs baseline: 2.6202x; 1.0585x over previous
#include <cuda_runtime.h>
#include <cuda_fp16.h>
#include <cstdint>

#define BATCH   16384
#define HID     512
#define NLAYERS 8
#define NOUT    16
#define WSCALE  4.4194173824159215e-04f  /* 0.01 / sqrt(512) */
#define BSCALE  0.01f
#define SLOPE   0.2f
#define GAIN    1.41421356237f
#define EPSV    1e-8f

// ---------------------------------------------------------------------------
// Scratch (allocation-free rule: __device__ globals)
// ---------------------------------------------------------------------------
__device__ __half g_Ahi[2][(size_t)BATCH * HID];
__device__ __half g_Alo[2][(size_t)BATCH * HID];
__device__ __half g_Whi[(size_t)NLAYERS * HID * HID];
__device__ __half g_Wlo[(size_t)NLAYERS * HID * HID];

// ---------------------------------------------------------------------------
// Helpers
// ---------------------------------------------------------------------------
__device__ __forceinline__ uint32_t smem_u32(const void* p) {
    uint32_t a;
    asm("{ .reg .u64 t; cvta.to.shared.u64 t, %1; cvt.u32.u64 %0, t; }"
        : "=r"(a) : "l"(p));
    return a;
}
__device__ __forceinline__ void ldm_x4(uint32_t addr, uint32_t r[4]) {
    asm volatile(
        "ldmatrix.sync.aligned.m8n8.x4.shared.b16 {%0,%1,%2,%3}, [%4];"
        : "=r"(r[0]), "=r"(r[1]), "=r"(r[2]), "=r"(r[3]) : "r"(addr));
}
__device__ __forceinline__ void mma16816(float c[4], const uint32_t a[4],
                                         const uint32_t b[2]) {
    asm volatile(
        "mma.sync.aligned.m16n8k16.row.col.f32.f16.f16.f32 "
        "{%0,%1,%2,%3}, {%4,%5,%6,%7}, {%8,%9}, {%0,%1,%2,%3};"
        : "+f"(c[0]), "+f"(c[1]), "+f"(c[2]), "+f"(c[3])
        : "r"(a[0]), "r"(a[1]), "r"(a[2]), "r"(a[3]), "r"(b[0]), "r"(b[1]));
}
#define CP_ASYNC16(sa, ga) \
    asm volatile("cp.async.cg.shared.global [%0], [%1], 16;" :: "r"(sa), "l"(ga))
#define CP_COMMIT() asm volatile("cp.async.commit_group;")
#define CP_WAIT1() asm volatile("cp.async.wait_group 1;")
#define CP_WAIT0() asm volatile("cp.async.wait_group 0;")

// ---------------------------------------------------------------------------
// Weight conversion: w_eff = w * WSCALE, split fp16 hi + lo
// ---------------------------------------------------------------------------
__global__ void wconv_kernel(const float* __restrict__ w,
                             __half* __restrict__ whi,
                             __half* __restrict__ wlo) {
    size_t i = (size_t)blockIdx.x * blockDim.x + threadIdx.x;
    float4 v = ((const float4*)w)[i];
    float e[4] = {v.x * WSCALE, v.y * WSCALE, v.z * WSCALE, v.w * WSCALE};
    union { uint2 u; __half h[4]; } ph, pl;
#pragma unroll
    for (int j = 0; j < 4; j++) {
        __half hh = __float2half_rn(e[j]);
        ph.h[j] = hh;
        pl.h[j] = __float2half_rn(e[j] - __half2float(hh));
    }
    ((uint2*)whi)[i] = ph.u;
    ((uint2*)wlo)[i] = pl.u;
}

// ---------------------------------------------------------------------------
// Pixel norm + fp16 hi/lo split
// ---------------------------------------------------------------------------
__global__ void pixelnorm_split_kernel(const float* __restrict__ z,
                                       __half* __restrict__ ahi,
                                       __half* __restrict__ alo) {
    const int row = blockIdx.x;
    const int tid = threadIdx.x;
    float4 v = ((const float4*)(z + (size_t)row * HID))[tid];
    float s = v.x * v.x + v.y * v.y + v.z * v.z + v.w * v.w;
#pragma unroll
    for (int o = 16; o > 0; o >>= 1) s += __shfl_xor_sync(0xffffffffu, s, o);
    __shared__ float ws[4];
    if ((tid & 31) == 0) ws[tid >> 5] = s;
    __syncthreads();
    float tot = ws[0] + ws[1] + ws[2] + ws[3];
    float r = rsqrtf(tot * (1.0f / HID) + EPSV);
    float e[4] = {v.x * r, v.y * r, v.z * r, v.w * r};
    union { uint2 u; __half h[4]; } ph, pl;
#pragma unroll
    for (int j = 0; j < 4; j++) {
        __half hh = __float2half_rn(e[j]);
        ph.h[j] = hh;
        pl.h[j] = __float2half_rn(e[j] - __half2float(hh));
    }
    size_t off = ((size_t)row * HID) / 4 + tid;
    ((uint2*)ahi)[off] = ph.u;
    ((uint2*)alo)[off] = pl.u;
}

// ---------------------------------------------------------------------------
// HMMA split-fp16 GEMM layer.  C[m,n] = sum_k a[m,k] * w_eff[n,k]
// 3 terms: hi*hi + hi*lo + lo*hi, fp32 accum.
// Tile BM=128 x BN=64, BK=32, 256 threads (4x2 warps, 32x32 per warp),
// 3 CTAs/SM (regs<=85, smem 60 KB).
// SMEM rows: 32 half = 64 B data, stride 80 B (conflict-free ldmatrix).
// ---------------------------------------------------------------------------
#define RSTRIDE 80
#define A_TILE_BYTES (128 * RSTRIDE)     /* 10240 */
#define B_TILE_BYTES (64 * RSTRIDE)      /* 5120 */
#define STAGE_BYTES (2 * A_TILE_BYTES + 2 * B_TILE_BYTES) /* 30720 */
#define SMEM_TOTAL (2 * STAGE_BYTES)     /* 61440 */
#define OFF_AH 0
#define OFF_AL A_TILE_BYTES
#define OFF_BH (2 * A_TILE_BYTES)
#define OFF_BL (2 * A_TILE_BYTES + B_TILE_BYTES)

// A tiles: 128 rows x 4 sixteen-byte units -> 512 cp.async, 2 per thread
__device__ __forceinline__ void load_tileA(uint32_t sbase,
                                           const __half* __restrict__ g,
                                           int rowbase, int kbase, int tid) {
#pragma unroll
    for (int h = 0; h < 2; h++) {
        int u = tid + h * 256;          // 0..511
        int row = u >> 2;
        int un = u & 3;
        uint32_t sa = sbase + row * RSTRIDE + un * 16;
        const void* ga = g + (size_t)(rowbase + row) * HID + kbase + un * 8;
        CP_ASYNC16(sa, ga);
    }
}
// B tiles: 64 rows x 4 units -> 256 cp.async, 1 per thread
__device__ __forceinline__ void load_tileB(uint32_t sbase,
                                           const __half* __restrict__ g,
                                           int rowbase, int kbase, int tid) {
    int row = tid >> 2;
    int un = tid & 3;
    uint32_t sa = sbase + row * RSTRIDE + un * 16;
    const void* ga = g + (size_t)(rowbase + row) * HID + kbase + un * 8;
    CP_ASYNC16(sa, ga);
}

template <bool LAST>
__global__ __launch_bounds__(256, 3) void gemm_layer(
    const __half* __restrict__ Ahi, const __half* __restrict__ Alo,
    const __half* __restrict__ Whi, const __half* __restrict__ Wlo,
    const float* __restrict__ bias, __half* __restrict__ Ohi,
    __half* __restrict__ Olo, float* __restrict__ OutF) {
    extern __shared__ char smem[];
    const uint32_t sb = smem_u32(smem);
    const int tid = threadIdx.x;
    const int wid = tid >> 5;
    const int lid = tid & 31;
    const int wm = wid >> 1;            // 0..3 -> 32 rows each
    const int wn = wid & 1;             // 0..1 -> 32 cols each
    const int bm = blockIdx.y * 128;
    const int bn = blockIdx.x * 64;

    // ldmatrix lane decomposition
    const int lt = lid >> 3;            // tile index 0..3
    const int li = lid & 7;             // row within 8x8 tile

    float acc[2][4][4];
#pragma unroll
    for (int a = 0; a < 2; a++)
#pragma unroll
        for (int b = 0; b < 4; b++)
#pragma unroll
            for (int c = 0; c < 4; c++) acc[a][b][c] = 0.0f;

    // prologue
    {
        load_tileA(sb + OFF_AH, Ahi, bm, 0, tid);
        load_tileA(sb + OFF_AL, Alo, bm, 0, tid);
        load_tileB(sb + OFF_BH, Whi, bn, 0, tid);
        load_tileB(sb + OFF_BL, Wlo, bn, 0, tid);
        CP_COMMIT();
    }

    for (int s = 0; s < 16; s++) {
        if (s + 1 < 16) {
            uint32_t sn = sb + ((s + 1) & 1) * STAGE_BYTES;
            int kb = (s + 1) * 32;
            load_tileA(sn + OFF_AH, Ahi, bm, kb, tid);
            load_tileA(sn + OFF_AL, Alo, bm, kb, tid);
            load_tileB(sn + OFF_BH, Whi, bn, kb, tid);
            load_tileB(sn + OFF_BL, Wlo, bn, kb, tid);
            CP_COMMIT();
            CP_WAIT1();
        } else {
            CP_WAIT0();
        }
        __syncthreads();

        uint32_t sc = sb + (s & 1) * STAGE_BYTES;
#pragma unroll
        for (int kk = 0; kk < 2; kk++) {
            // A fragments: x4 tiles -> m_off=(lt&1)*8, k_off=(lt>>1)*8
            const int am_row = wm * 32 + (lt & 1) * 8 + li;
            const int ak = kk * 16 + (lt >> 1) * 8;
            uint32_t ah[2][4], al[2][4];
#pragma unroll
            for (int mf = 0; mf < 2; mf++) {
                uint32_t addr =
                    sc + OFF_AH + (am_row + mf * 16) * RSTRIDE + ak * 2;
                ldm_x4(addr, ah[mf]);
                ldm_x4(addr + (OFF_AL - OFF_AH), al[mf]);
            }
            // B fragments: x4 -> n_off=(lt>>1)*8, k_off=(lt&1)*8
            const int bn_row0 = wn * 32 + (lt >> 1) * 8 + li;
            const int bk = kk * 16 + (lt & 1) * 8;
            uint32_t bh[4][2], bl[4][2];
#pragma unroll
            for (int p = 0; p < 2; p++) {
                uint32_t addr =
                    sc + OFF_BH + (bn_row0 + p * 16) * RSTRIDE + bk * 2;
                uint32_t r[4];
                ldm_x4(addr, r);
                bh[2 * p][0] = r[0]; bh[2 * p][1] = r[1];
                bh[2 * p + 1][0] = r[2]; bh[2 * p + 1][1] = r[3];
                ldm_x4(addr + (OFF_BL - OFF_BH), r);
                bl[2 * p][0] = r[0]; bl[2 * p][1] = r[1];
                bl[2 * p + 1][0] = r[2]; bl[2 * p + 1][1] = r[3];
            }
            // term-outer ordering: 8 independent accumulators between
            // same-acc reuses
#pragma unroll
            for (int mf = 0; mf < 2; mf++)
#pragma unroll
                for (int nf = 0; nf < 4; nf++)
                    mma16816(acc[mf][nf], ah[mf], bh[nf]);
#pragma unroll
            for (int mf = 0; mf < 2; mf++)
#pragma unroll
                for (int nf = 0; nf < 4; nf++)
                    mma16816(acc[mf][nf], ah[mf], bl[nf]);
#pragma unroll
            for (int mf = 0; mf < 2; mf++)
#pragma unroll
                for (int nf = 0; nf < 4; nf++)
                    mma16816(acc[mf][nf], al[mf], bh[nf]);
        }
        __syncthreads();
    }

    // Epilogue: m16n8 c mapping: reg e -> row=(l/4)+(e>=2?8:0),
    // col=(l%4)*2+(e&1)
    float bj[4][2];
#pragma unroll
    for (int nf = 0; nf < 4; nf++) {
        int col = bn + wn * 32 + nf * 8 + (lid & 3) * 2;
        bj[nf][0] = bias[col] * BSCALE;
        bj[nf][1] = bias[col + 1] * BSCALE;
    }

#pragma unroll
    for (int mf = 0; mf < 2; mf++) {
#pragma unroll
        for (int half_ : {0, 1}) {
            int row = bm + wm * 32 + mf * 16 + (lid >> 2) + half_ * 8;
#pragma unroll
            for (int nf = 0; nf < 4; nf++) {
                int col = bn + wn * 32 + nf * 8 + (lid & 3) * 2;
                float x0 = acc[mf][nf][half_ * 2 + 0] + bj[nf][0];
                float x1 = acc[mf][nf][half_ * 2 + 1] + bj[nf][1];
                x0 = (x0 > 0.0f ? x0 : SLOPE * x0) * GAIN;
                x1 = (x1 > 0.0f ? x1 : SLOPE * x1) * GAIN;
                if (!LAST) {
                    __half h0 = __float2half_rn(x0);
                    __half h1 = __float2half_rn(x1);
                    __half l0 = __float2half_rn(x0 - __half2float(h0));
                    __half l1 = __float2half_rn(x1 - __half2float(h1));
                    size_t off = (size_t)row * HID + col;
                    *(__half2*)(Ohi + off) = __halves2half2(h0, h1);
                    *(__half2*)(Olo + off) = __halves2half2(l0, l1);
                } else {
                    float2 p = make_float2(x0, x1);
#pragma unroll
                    for (int r = 0; r < NOUT; r++) {
                        size_t off = ((size_t)row * NOUT + r) * HID + col;
                        *(float2*)(OutF + off) = p;
                    }
                }
            }
        }
    }
}

// ---------------------------------------------------------------------------
extern "C" void kernel_launch(void* const* d_in, const int* in_sizes, int n_in,
                              void* d_out, int out_size) {
    const float* z = (const float*)d_in[0];
    const float* weight = (const float*)d_in[1];
    const float* bias = (const float*)d_in[2];
    float* out = (float*)d_out;

    __half *ahi, *alo, *whi, *wlo;
    cudaGetSymbolAddress((void**)&ahi, g_Ahi);
    cudaGetSymbolAddress((void**)&alo, g_Alo);
    cudaGetSymbolAddress((void**)&whi, g_Whi);
    cudaGetSymbolAddress((void**)&wlo, g_Wlo);

    cudaFuncSetAttribute(gemm_layer<false>,
                         cudaFuncAttributeMaxDynamicSharedMemorySize, SMEM_TOTAL);
    cudaFuncSetAttribute(gemm_layer<true>,
                         cudaFuncAttributeMaxDynamicSharedMemorySize, SMEM_TOTAL);

    wconv_kernel<<<2048, 256>>>(weight, whi, wlo);
    pixelnorm_split_kernel<<<BATCH, 128>>>(z, ahi, alo);

    const size_t ABUF = (size_t)BATCH * HID;
    dim3 grid(HID / 64, BATCH / 128);   // (8, 128) = 1024 CTAs
    for (int l = 0; l < NLAYERS; l++) {
        const __half* Ah = ahi + (l & 1) * ABUF;
        const __half* Al = alo + (l & 1) * ABUF;
        __half* Oh = ahi + ((l + 1) & 1) * ABUF;
        __half* Ol = alo + ((l + 1) & 1) * ABUF;
        const __half* Wh = whi + (size_t)l * HID * HID;
        const __half* Wl = wlo + (size_t)l * HID * HID;
        const float* bl = bias + (size_t)l * HID;
        if (l == NLAYERS - 1)
            gemm_layer<true><<<grid, 256, SMEM_TOTAL>>>(Ah, Al, Wh, Wl, bl,
                                                        nullptr, nullptr, out);
        else
            gemm_layer<false><<<grid, 256, SMEM_TOTAL>>>(Ah, Al, Wh, Wl, bl,
                                                         Oh, Ol, nullptr);
    }
}